// round 10
// baseline (speedup 1.0000x reference)
#include <cuda_runtime.h>
#include <cuda_bf16.h>
#include <cstdint>

// masksampling: out = (mask1, mask2), each (32,3,1024,1024) fp32.
// fm[b, 2i+p, 2j+q] = PATTERNS[initmask[b,0,i,j], p, q]
// mask1 = (fm==1), mask2 = (fm==2), broadcast over c=3.
// Pure store-bandwidth kernel: 805 MB written; initmask reads L2-resident.
// x (d_in[0]) is never touched.
//
// R10: combine the two proven wins.
//  - STG.256 stores, R6 mapping (4 initmask cols/thread, both masks, 12 stores)
//    -> best kernel-internal DRAM% measured (81.1)
//  - BLK=128 (R9 win: more CTAs -> more independent store contexts)
//  => 16384 CTAs x 128 thr, ~40 regs -> occ ~75%, per-thread 384B in flight.

// PATTERNS packed little-endian: byte (p*2+q) = PATTERNS[k][p][q]
__constant__ unsigned int c_pat[4] = {0x00000201u, 0x02000100u, 0x01020000u, 0x00010002u};

static constexpr int B = 32;
static constexpr int C = 3;
static constexpr int W = 1024;
static constexpr int H = 1024;
static constexpr int WI = W / 2;    // 512 initmask rows
static constexpr int HI = H / 2;    // 512 initmask cols
static constexpr int TPR = HI / 4;  // 128 threads per initmask row (4 cols/thread)
static constexpr int BLK = 128;

__device__ __forceinline__ void stg256_cs(float* p, const float* v) {
    asm volatile(
        "st.global.cs.v8.f32 [%0], {%1, %2, %3, %4, %5, %6, %7, %8};"
        :: "l"(p),
           "f"(v[0]), "f"(v[1]), "f"(v[2]), "f"(v[3]),
           "f"(v[4]), "f"(v[5]), "f"(v[6]), "f"(v[7])
        : "memory");
}

__global__ void __launch_bounds__(BLK)
masksampling_kernel(const void* __restrict__ im_raw, float* __restrict__ out) {
    // ---- in-kernel dtype detection (jax may downcast int64 -> int32) ----
    // int64 little-endian values 0..3 have ALL odd dwords == 0. Random int32
    // values 0..3 have a nonzero odd dword with prob 1 - 4^-32 over 32 samples.
    __shared__ unsigned s_nz;
    if (threadIdx.x == 0) s_nz = 0u;
    __syncthreads();
    if (threadIdx.x < 32) {
        unsigned v = reinterpret_cast<const unsigned*>(im_raw)[2u * threadIdx.x + 1u];
        if (v) atomicOr(&s_nz, 1u);
    }
    __syncthreads();
    const bool is_i64 = (s_nz == 0u);

    unsigned tid = blockIdx.x * (unsigned)BLK + threadIdx.x;
    // tid layout: b (32) | i (512) | t (128)
    unsigned t = tid & (TPR - 1);
    unsigned i = (tid >> 7) & (WI - 1);
    unsigned b = tid >> 16;

    size_t im_idx = (size_t)b * (WI * HI) + (size_t)i * HI + 4u * t;

    int m0, m1, m2, m3;
    if (is_i64) {
        const long long* p64 = reinterpret_cast<const long long*>(im_raw) + im_idx;
        const longlong2 q0 = __ldg(reinterpret_cast<const longlong2*>(p64));
        const longlong2 q1 = __ldg(reinterpret_cast<const longlong2*>(p64 + 2));
        m0 = (int)q0.x; m1 = (int)q0.y; m2 = (int)q1.x; m3 = (int)q1.y;
    } else {
        const int4 mv = __ldg(reinterpret_cast<const int4*>(
            reinterpret_cast<const int*>(im_raw) + im_idx));
        m0 = mv.x; m1 = mv.y; m2 = mv.z; m3 = mv.w;
    }

    unsigned pw[4];
    pw[0] = c_pat[m0]; pw[1] = c_pat[m1]; pw[2] = c_pat[m2]; pw[3] = c_pat[m3];

    const size_t rowbase = (size_t)(2u * i) * H + 8u * t;

    #pragma unroll
    for (int m = 0; m < 2; m++) {
        const unsigned target = (unsigned)(m + 1);
        // r0 = row 2i, r1 = row 2i+1, cols 8t..8t+7
        float r0[8], r1[8];
        #pragma unroll
        for (int k = 0; k < 4; k++) {
            r0[2 * k]     = ((pw[k] >> 0)  & 0xffu) == target ? 1.f : 0.f;
            r0[2 * k + 1] = ((pw[k] >> 8)  & 0xffu) == target ? 1.f : 0.f;
            r1[2 * k]     = ((pw[k] >> 16) & 0xffu) == target ? 1.f : 0.f;
            r1[2 * k + 1] = ((pw[k] >> 24) & 0xffu) == target ? 1.f : 0.f;
        }
        #pragma unroll
        for (int c = 0; c < C; c++) {
            size_t base = ((size_t)(m * B + b) * C + c) * (size_t)(W * H) + rowbase;
            stg256_cs(out + base, r0);
            stg256_cs(out + base + H, r1);
        }
    }
}

extern "C" void kernel_launch(void* const* d_in, const int* in_sizes, int n_in,
                              void* d_out, int out_size) {
    // d_in[0] = x (unused), d_in[1] = initmask (int64 or int32, values 0..3)
    const void* im = d_in[1];
    float* out = (float*)d_out;

    const unsigned total_threads = B * WI * TPR;  // 2,097,152
    masksampling_kernel<<<total_threads / BLK, BLK>>>(im, out);
}

// round 11
// speedup vs baseline: 1.0052x; 1.0052x over previous
#include <cuda_runtime.h>
#include <cuda_bf16.h>
#include <cstdint>

// masksampling: out = (mask1, mask2), each (32,3,1024,1024) fp32.
// fm[b, 2i+p, 2j+q] = PATTERNS[initmask[b,0,i,j], p, q]
// mask1 = (fm==1), mask2 = (fm==2), broadcast over c=3.
// Pure store-bandwidth kernel: 805 MB written; initmask reads L2-resident.
// x (d_in[0]) is never touched.
//
// R11: extend R9's proven lever (CTA count). R9 mapping unchanged (2 initmask
// cols/thread, both masks, float4 .cs stores, 28 regs), BLK 128 -> 64 =>
// 65536 CTAs. BLK 256->128 gave -0.9us/+1.6 DRAM pts; testing whether the
// trend continues or saturates. STG.256 retired for good (3x no harness win).

// PATTERNS packed little-endian: byte (p*2+q) = PATTERNS[k][p][q]
__constant__ unsigned int c_pat[4] = {0x00000201u, 0x02000100u, 0x01020000u, 0x00010002u};

static constexpr int B = 32;
static constexpr int C = 3;
static constexpr int W = 1024;
static constexpr int H = 1024;
static constexpr int WI = W / 2;   // 512 initmask rows
static constexpr int HI = H / 2;   // 512 initmask cols
static constexpr int TPR = HI / 2; // 256 threads per initmask row (2 cols/thread)
static constexpr int BLK = 64;

__global__ void __launch_bounds__(BLK)
masksampling_kernel(const void* __restrict__ im_raw, float* __restrict__ out) {
    // ---- in-kernel dtype detection (jax may downcast int64 -> int32) ----
    // int64 little-endian values 0..3 have ALL odd dwords == 0. Random int32
    // values 0..3 have a nonzero odd dword with prob 1 - 4^-32 over 32 samples.
    __shared__ unsigned s_nz;
    if (threadIdx.x == 0) s_nz = 0u;
    __syncthreads();
    if (threadIdx.x < 32) {
        unsigned v = reinterpret_cast<const unsigned*>(im_raw)[2u * threadIdx.x + 1u];
        if (v) atomicOr(&s_nz, 1u);
    }
    __syncthreads();
    const bool is_i64 = (s_nz == 0u);

    unsigned tid = blockIdx.x * (unsigned)BLK + threadIdx.x;
    // tid layout: b (32) | i (512) | t (256)
    unsigned t = tid & (TPR - 1);
    unsigned i = (tid >> 8) & (WI - 1);
    unsigned b = tid >> 17;

    size_t im_idx = (size_t)b * (WI * HI) + (size_t)i * HI + 2u * t;

    int m0, m1;
    if (is_i64) {
        const longlong2 mv = __ldg(reinterpret_cast<const longlong2*>(
            reinterpret_cast<const long long*>(im_raw) + im_idx));
        m0 = (int)mv.x;
        m1 = (int)mv.y;
    } else {
        const int2 mv = __ldg(reinterpret_cast<const int2*>(
            reinterpret_cast<const int*>(im_raw) + im_idx));
        m0 = mv.x;
        m1 = mv.y;
    }

    const unsigned pa = c_pat[m0];
    const unsigned pb = c_pat[m1];

    // v[mask][p] : 4 output floats at row 2i+p, cols 4t..4t+3
    float4 v[2][2];
    #pragma unroll
    for (int p = 0; p < 2; p++) {
        unsigned a0 = (pa >> (p * 16)) & 0xffu;
        unsigned a1 = (pa >> (p * 16 + 8)) & 0xffu;
        unsigned b0 = (pb >> (p * 16)) & 0xffu;
        unsigned b1 = (pb >> (p * 16 + 8)) & 0xffu;
        v[0][p] = make_float4(a0 == 1u ? 1.f : 0.f, a1 == 1u ? 1.f : 0.f,
                              b0 == 1u ? 1.f : 0.f, b1 == 1u ? 1.f : 0.f);
        v[1][p] = make_float4(a0 == 2u ? 1.f : 0.f, a1 == 2u ? 1.f : 0.f,
                              b0 == 2u ? 1.f : 0.f, b1 == 2u ? 1.f : 0.f);
    }

    const size_t rowbase = (size_t)(2u * i) * H + 4u * t;
    #pragma unroll
    for (int m = 0; m < 2; m++) {
        #pragma unroll
        for (int c = 0; c < C; c++) {
            size_t base = ((size_t)(m * B + b) * C + c) * (size_t)(W * H) + rowbase;
            __stcs(reinterpret_cast<float4*>(out + base), v[m][0]);
            __stcs(reinterpret_cast<float4*>(out + base + H), v[m][1]);
        }
    }
}

extern "C" void kernel_launch(void* const* d_in, const int* in_sizes, int n_in,
                              void* d_out, int out_size) {
    // d_in[0] = x (unused), d_in[1] = initmask (int64 or int32, values 0..3)
    const void* im = d_in[1];
    float* out = (float*)d_out;

    const unsigned total_threads = B * WI * TPR;  // 4,194,304
    masksampling_kernel<<<total_threads / BLK, BLK>>>(im, out);
}

// round 12
// speedup vs baseline: 1.0055x; 1.0003x over previous
#include <cuda_runtime.h>
#include <cuda_bf16.h>
#include <cstdint>

// masksampling: out = (mask1, mask2), each (32,3,1024,1024) fp32.
// fm[b, 2i+p, 2j+q] = PATTERNS[initmask[b,0,i,j], p, q]
// mask1 = (fm==1), mask2 = (fm==2), broadcast over c=3.
// Pure store-bandwidth kernel: 805 MB written; initmask reads L2-resident.
// x (d_in[0]) is never touched.
//
// R12: R9 winner (BLK=128 / 32768 CTAs / float4 .cs / 28 regs -> 122.46us)
// with barrier-free dtype detection: each warp ballots over 32 odd dwords of
// the initmask head (one hot 128B L2 line chip-wide). Removes 2x BAR.SYNC,
// the atomicOr and the smem word; warps start storing immediately.
// Lever map (final): block 128 optimal (256:+0.9, 64:+0.5), .cs == plain > .wt,
// 128-bit stores > 256-bit in steady state, full grid >> persistent.

// PATTERNS packed little-endian: byte (p*2+q) = PATTERNS[k][p][q]
__constant__ unsigned int c_pat[4] = {0x00000201u, 0x02000100u, 0x01020000u, 0x00010002u};

static constexpr int B = 32;
static constexpr int C = 3;
static constexpr int W = 1024;
static constexpr int H = 1024;
static constexpr int WI = W / 2;   // 512 initmask rows
static constexpr int HI = H / 2;   // 512 initmask cols
static constexpr int TPR = HI / 2; // 256 threads per initmask row (2 cols/thread)
static constexpr int BLK = 128;

__global__ void __launch_bounds__(BLK)
masksampling_kernel(const void* __restrict__ im_raw, float* __restrict__ out) {
    // ---- barrier-free dtype detection (jax may downcast int64 -> int32) ----
    // int64 little-endian values 0..3 have ALL odd dwords == 0. Random int32
    // values 0..3: nonzero odd dword with prob 1 - 4^-32 over 32 samples.
    // Per-warp: lane k reads odd dword k (all 32 from one hot 128B+ region,
    // L2-broadcast), then ballot. No smem, no block barrier.
    const unsigned lane = threadIdx.x & 31u;
    const unsigned v = __ldg(reinterpret_cast<const unsigned*>(im_raw) + 2u * lane + 1u);
    const bool is_i64 = (__ballot_sync(0xffffffffu, v != 0u) == 0u);

    unsigned tid = blockIdx.x * (unsigned)BLK + threadIdx.x;
    // tid layout: b (32) | i (512) | t (256)
    unsigned t = tid & (TPR - 1);
    unsigned i = (tid >> 8) & (WI - 1);
    unsigned b = tid >> 17;

    size_t im_idx = (size_t)b * (WI * HI) + (size_t)i * HI + 2u * t;

    int m0, m1;
    if (is_i64) {
        const longlong2 mv = __ldg(reinterpret_cast<const longlong2*>(
            reinterpret_cast<const long long*>(im_raw) + im_idx));
        m0 = (int)mv.x;
        m1 = (int)mv.y;
    } else {
        const int2 mv = __ldg(reinterpret_cast<const int2*>(
            reinterpret_cast<const int*>(im_raw) + im_idx));
        m0 = mv.x;
        m1 = mv.y;
    }

    const unsigned pa = c_pat[m0];
    const unsigned pb = c_pat[m1];

    // v[mask][p] : 4 output floats at row 2i+p, cols 4t..4t+3
    float4 vv[2][2];
    #pragma unroll
    for (int p = 0; p < 2; p++) {
        unsigned a0 = (pa >> (p * 16)) & 0xffu;
        unsigned a1 = (pa >> (p * 16 + 8)) & 0xffu;
        unsigned b0 = (pb >> (p * 16)) & 0xffu;
        unsigned b1 = (pb >> (p * 16 + 8)) & 0xffu;
        vv[0][p] = make_float4(a0 == 1u ? 1.f : 0.f, a1 == 1u ? 1.f : 0.f,
                               b0 == 1u ? 1.f : 0.f, b1 == 1u ? 1.f : 0.f);
        vv[1][p] = make_float4(a0 == 2u ? 1.f : 0.f, a1 == 2u ? 1.f : 0.f,
                               b0 == 2u ? 1.f : 0.f, b1 == 2u ? 1.f : 0.f);
    }

    const size_t rowbase = (size_t)(2u * i) * H + 4u * t;
    #pragma unroll
    for (int m = 0; m < 2; m++) {
        #pragma unroll
        for (int c = 0; c < C; c++) {
            size_t base = ((size_t)(m * B + b) * C + c) * (size_t)(W * H) + rowbase;
            __stcs(reinterpret_cast<float4*>(out + base), vv[m][0]);
            __stcs(reinterpret_cast<float4*>(out + base + H), vv[m][1]);
        }
    }
}

extern "C" void kernel_launch(void* const* d_in, const int* in_sizes, int n_in,
                              void* d_out, int out_size) {
    // d_in[0] = x (unused), d_in[1] = initmask (int64 or int32, values 0..3)
    const void* im = d_in[1];
    float* out = (float*)d_out;

    const unsigned total_threads = B * WI * TPR;  // 4,194,304
    masksampling_kernel<<<total_threads / BLK, BLK>>>(im, out);
}

// round 13
// speedup vs baseline: 1.0118x; 1.0063x over previous
#include <cuda_runtime.h>
#include <cuda_bf16.h>
#include <cstdint>

// masksampling: out = (mask1, mask2), each (32,3,1024,1024) fp32.
// fm[b, 2i+p, 2j+q] = PATTERNS[initmask[b,0,i,j], p, q]
// mask1 = (fm==1), mask2 = (fm==2), broadcast over c=3.
// Pure store-bandwidth kernel: 805 MB written; initmask reads L2-resident.
// x (d_in[0]) is never touched.
//
// R13 == R9 verbatim — measured best (122.46us), locked in after mapping every
// lever: BLK=128/32768 CTAs (256:+0.9, 64:+0.5), float4 .cs stores (STG.256:
// no harness win x3; .wt:+4us; persistent grid:+19us), block-shared detection
// (per-warp ballot:+0.5us). 80.4% DRAM = streaming-write ceiling on B300.

// PATTERNS packed little-endian: byte (p*2+q) = PATTERNS[k][p][q]
__constant__ unsigned int c_pat[4] = {0x00000201u, 0x02000100u, 0x01020000u, 0x00010002u};

static constexpr int B = 32;
static constexpr int C = 3;
static constexpr int W = 1024;
static constexpr int H = 1024;
static constexpr int WI = W / 2;   // 512 initmask rows
static constexpr int HI = H / 2;   // 512 initmask cols
static constexpr int TPR = HI / 2; // 256 threads per initmask row (2 cols/thread)
static constexpr int BLK = 128;

__global__ void __launch_bounds__(BLK)
masksampling_kernel(const void* __restrict__ im_raw, float* __restrict__ out) {
    // ---- in-kernel dtype detection (jax may downcast int64 -> int32) ----
    // int64 little-endian values 0..3 have ALL odd dwords == 0. Random int32
    // values 0..3 have a nonzero odd dword with prob 1 - 4^-32 over 32 samples.
    __shared__ unsigned s_nz;
    if (threadIdx.x == 0) s_nz = 0u;
    __syncthreads();
    if (threadIdx.x < 32) {
        unsigned v = reinterpret_cast<const unsigned*>(im_raw)[2u * threadIdx.x + 1u];
        if (v) atomicOr(&s_nz, 1u);
    }
    __syncthreads();
    const bool is_i64 = (s_nz == 0u);

    unsigned tid = blockIdx.x * (unsigned)BLK + threadIdx.x;
    // tid layout: b (32) | i (512) | t (256)
    unsigned t = tid & (TPR - 1);
    unsigned i = (tid >> 8) & (WI - 1);
    unsigned b = tid >> 17;

    size_t im_idx = (size_t)b * (WI * HI) + (size_t)i * HI + 2u * t;

    int m0, m1;
    if (is_i64) {
        const longlong2 mv = __ldg(reinterpret_cast<const longlong2*>(
            reinterpret_cast<const long long*>(im_raw) + im_idx));
        m0 = (int)mv.x;
        m1 = (int)mv.y;
    } else {
        const int2 mv = __ldg(reinterpret_cast<const int2*>(
            reinterpret_cast<const int*>(im_raw) + im_idx));
        m0 = mv.x;
        m1 = mv.y;
    }

    const unsigned pa = c_pat[m0];
    const unsigned pb = c_pat[m1];

    // v[mask][p] : 4 output floats at row 2i+p, cols 4t..4t+3
    float4 v[2][2];
    #pragma unroll
    for (int p = 0; p < 2; p++) {
        unsigned a0 = (pa >> (p * 16)) & 0xffu;
        unsigned a1 = (pa >> (p * 16 + 8)) & 0xffu;
        unsigned b0 = (pb >> (p * 16)) & 0xffu;
        unsigned b1 = (pb >> (p * 16 + 8)) & 0xffu;
        v[0][p] = make_float4(a0 == 1u ? 1.f : 0.f, a1 == 1u ? 1.f : 0.f,
                              b0 == 1u ? 1.f : 0.f, b1 == 1u ? 1.f : 0.f);
        v[1][p] = make_float4(a0 == 2u ? 1.f : 0.f, a1 == 2u ? 1.f : 0.f,
                              b0 == 2u ? 1.f : 0.f, b1 == 2u ? 1.f : 0.f);
    }

    const size_t rowbase = (size_t)(2u * i) * H + 4u * t;
    #pragma unroll
    for (int m = 0; m < 2; m++) {
        #pragma unroll
        for (int c = 0; c < C; c++) {
            size_t base = ((size_t)(m * B + b) * C + c) * (size_t)(W * H) + rowbase;
            __stcs(reinterpret_cast<float4*>(out + base), v[m][0]);
            __stcs(reinterpret_cast<float4*>(out + base + H), v[m][1]);
        }
    }
}

extern "C" void kernel_launch(void* const* d_in, const int* in_sizes, int n_in,
                              void* d_out, int out_size) {
    // d_in[0] = x (unused), d_in[1] = initmask (int64 or int32, values 0..3)
    const void* im = d_in[1];
    float* out = (float*)d_out;

    const unsigned total_threads = B * WI * TPR;  // 4,194,304
    masksampling_kernel<<<total_threads / BLK, BLK>>>(im, out);
}